// round 6
// baseline (speedup 1.0000x reference)
#include <cuda_runtime.h>
#include <cstdint>
#include <math.h>

#define LEVELS 3
#define BINS 9
#define NATOMS 51
#define ADIM 6
#define NB 4096
#define ROWS 162                          // LEVELS*ADIM*BINS
#define SLAB 8262                         // ROWS*NATOMS floats
#define SLAB_BYTES 33048                  // == 8 mod 16
#define SLOT_BYTES 33056                  // 16B-rounded slab slot
#define V_MIN_C (-10.0f)
#define V_MAX_C (10.0f)
#define DZ_C (0.4f)

#define THREADS 256
#define SLABS_PER_CTA 4
#define GRID (NB / SLABS_PER_CTA)         // 1024

// dynamic smem layout (bytes), 16B aligned base:
//   [0,32)                    2 mbarriers (8B each, padded)
//   [32, 32+2*SLOT)           input slots 0,1
//   [32+2*SLOT, 32+4*SLOT)    output slots 0,1
#define OFF_MBAR 0
#define OFF_IN   32
#define OFF_OUT  (32 + 2 * SLOT_BYTES)    // 66144
#define DYN_BYTES (32 + 4 * SLOT_BYTES)   // 132256

__global__ __launch_bounds__(THREADS)
void c2f_kernel(const float* __restrict__ q,
                const float* __restrict__ reward,
                const float* __restrict__ discount,
                const float* __restrict__ act,
                const float* __restrict__ support,
                const float* __restrict__ low0,
                const float* __restrict__ high0,
                float* __restrict__ out)
{
    const int c = blockIdx.x;
    const int t = threadIdx.x;
    const int g0 = c * SLABS_PER_CTA;     // even -> group base 16B aligned

    extern __shared__ __align__(16) char dyn[];
    const uint32_t smem_base = (uint32_t)__cvta_generic_to_shared(dyn);

    __shared__ float swl[NATOMS];
    __shared__ float swu[NATOMS];
    __shared__ int   slower[NATOMS];

    if (t == 0) {
        asm volatile("mbarrier.init.shared.b64 [%0], 1;" :: "r"(smem_base + OFF_MBAR) : "memory");
        asm volatile("mbarrier.init.shared.b64 [%0], 1;" :: "r"(smem_base + OFF_MBAR + 8) : "memory");
    }
    __syncthreads();

    // ---- prolog: issue TMA load of slab g0 into input slot 0 (m=0) ----
    if (t == 0) {
        const char* src = reinterpret_cast<const char*>(q) + (size_t)g0 * SLAB_BYTES;
        asm volatile("mbarrier.arrive.expect_tx.shared.b64 _, [%0], %1;"
                     :: "r"(smem_base + OFF_MBAR), "r"((uint32_t)SLOT_BYTES) : "memory");
        asm volatile("cp.async.bulk.shared::cta.global.mbarrier::complete_tx::bytes "
                     "[%0], [%1], %2, [%3];"
                     :: "r"(smem_base + OFF_IN), "l"(src),
                        "r"((uint32_t)SLOT_BYTES), "r"(smem_base + OFF_MBAR) : "memory");
    }

    #pragma unroll 1
    for (int i = 0; i < SLABS_PER_CTA; i++) {
        const int g = g0 + i;
        const int m = (i & 1) ? 8 : 0;                 // slab misalignment mod 16
        const uint32_t in_slot  = smem_base + OFF_IN  + (uint32_t)(i & 1) * SLOT_BYTES;
        const uint32_t out_slot = smem_base + OFF_OUT + (uint32_t)(i & 1) * SLOT_BYTES;
        float* sp = reinterpret_cast<float*>(dyn + OFF_IN  + (i & 1) * SLOT_BYTES + m);
        float* so = reinterpret_cast<float*>(dyn + OFF_OUT + (i & 1) * SLOT_BYTES + m);

        // ---- per-slab projection tables (block-uniform) ----
        if (t < NATOMS) {
            const float r = reward[g];
            const float d = discount[g];
            const float z = support[t];
            float Tz = fminf(fmaxf(r + d * z, V_MIN_C), V_MAX_C);
            float bc = (Tz - V_MIN_C) / DZ_C;
            int lo = (int)floorf(bc);
            int up = (int)ceilf(bc);
            if (up > 0 && lo == up) lo -= 1;           // reference fixup 1
            if (lo < NATOMS - 1 && lo == up) up += 1;  // reference fixup 2 => up==lo+1
            slower[t] = lo;                            // in [0,49]
            swl[t] = (float)up - bc;
            swu[t] = bc - (float)lo;
        }

        // ---- encode + decode (6 dims) ----
        if (t >= 64 && t < 64 + ADIM) {
            const int dim = t - 64;
            const float a = act[g * ADIM + dim];
            float low = low0[dim], high = high0[dim];
            float idx[LEVELS];
            #pragma unroll
            for (int lvl = 0; lvl < LEVELS; lvl++) {
                float sr = (high - low) / (float)BINS;
                float id = floorf((a - low) / sr);
                id = fminf(fmaxf(id, 0.0f), (float)(BINS - 1));
                float na = fminf(fmaxf(low + sr * id, -1.0f), 1.0f);
                low  = fmaxf(-1.0f, na);
                high = fminf(1.0f, na + sr);
                idx[lvl] = id;
            }
            low = low0[dim]; high = high0[dim];
            #pragma unroll
            for (int lvl = 0; lvl < LEVELS; lvl++) {
                float sr = (high - low) / (float)BINS;
                float cont = low + sr * idx[lvl];
                low  = fmaxf(-1.0f, cont);
                high = fminf(1.0f, cont + sr);
            }
            out[(size_t)NB * SLAB + (size_t)g * ADIM + dim] = 0.5f * (high + low);
        }

        if (t == 0) {
            // ---- issue next slab's load into the other input slot ----
            if (i + 1 < SLABS_PER_CTA) {
                const int mn = ((i + 1) & 1) ? 8 : 0;
                const uint32_t nbar  = smem_base + OFF_MBAR + (uint32_t)((i + 1) & 1) * 8;
                const uint32_t nslot = smem_base + OFF_IN   + (uint32_t)((i + 1) & 1) * SLOT_BYTES;
                const char* src = reinterpret_cast<const char*>(q)
                                + (size_t)(g + 1) * SLAB_BYTES - mn;
                asm volatile("mbarrier.arrive.expect_tx.shared.b64 _, [%0], %1;"
                             :: "r"(nbar), "r"((uint32_t)SLOT_BYTES) : "memory");
                asm volatile("cp.async.bulk.shared::cta.global.mbarrier::complete_tx::bytes "
                             "[%0], [%1], %2, [%3];"
                             :: "r"(nslot), "l"(src),
                                "r"((uint32_t)SLOT_BYTES), "r"(nbar) : "memory");
            }
            // ---- recycle this iteration's output slot (store from slab i-2) ----
            asm volatile("cp.async.bulk.wait_group 1;" ::: "memory");
        }
        __syncthreads();   // tables ready, out-slot free

        // ---- wait for input slab i ----
        {
            const uint32_t bar = smem_base + OFF_MBAR + (uint32_t)(i & 1) * 8;
            const uint32_t ph = (uint32_t)((i >> 1) & 1);
            asm volatile(
                "{\n\t"
                ".reg .pred P;\n\t"
                "WAIT_%=:\n\t"
                "mbarrier.try_wait.parity.acquire.cta.shared::cta.b64 P, [%0], %1, 0x989680;\n\t"
                "@!P bra WAIT_%=;\n\t"
                "}"
                :: "r"(bar), "r"(ph) : "memory");
        }

        // ---- walk: one thread per row, single pass j=0..50, gap zero-fill ----
        if (t < ROWS) {
            const float* pr = sp + t * NATOMS;   // stride 51 (odd) -> conflict-free
            float* po = so + t * NATOMS;
            int kcur = slower[0];
            for (int k = 0; k < kcur; k++) po[k] = 0.0f;
            float accA = 0.0f, accB = 0.0f, carryB = 0.0f;
            #pragma unroll 1
            for (int j = 0; j < NATOMS; j++) {
                const int kj = slower[j];        // uniform broadcast
                if (kj != kcur) {                // uniform branch
                    po[kcur] = accA + carryB;
                    if (kj == kcur + 1) {
                        carryB = accB;
                    } else {
                        po[kcur + 1] = accB;
                        for (int k = kcur + 2; k < kj; k++) po[k] = 0.0f;
                        carryB = 0.0f;
                    }
                    accA = 0.0f; accB = 0.0f; kcur = kj;
                }
                const float p = pr[j];
                accA = fmaf(p, swl[j], accA);
                accB = fmaf(p, swu[j], accB);
            }
            po[kcur] = accA + carryB;
            po[kcur + 1] = accB;                 // kcur <= 49 -> safe
            for (int k = kcur + 2; k < NATOMS; k++) po[k] = 0.0f;
        }
        __syncthreads();

        // ---- bulk store aligned interior + 2 scalar floats ----
        if (t == 0) {
            float* dst = out + (size_t)g * SLAB;
            if (m == 8) { dst[0] = so[0]; dst[1] = so[1]; }
            else        { dst[SLAB - 2] = so[SLAB - 2]; dst[SLAB - 1] = so[SLAB - 1]; }
            asm volatile("fence.proxy.async.shared::cta;" ::: "memory");
            const uint32_t src_s = out_slot + ((m == 8) ? 16u : 0u);
            char* dst_al = reinterpret_cast<char*>(out) + (size_t)g * SLAB_BYTES
                         + ((m == 8) ? 8 : 0);
            asm volatile("cp.async.bulk.global.shared::cta.bulk_group [%0], [%1], %2;"
                         :: "l"(dst_al), "r"(src_s), "r"((uint32_t)33040) : "memory");
            asm volatile("cp.async.bulk.commit_group;" ::: "memory");
        }
    }

    // ---- epilog: drain outstanding bulk stores before exit ----
    if (t == 0) {
        asm volatile("cp.async.bulk.wait_group 0;" ::: "memory");
    }
}

extern "C" void kernel_launch(void* const* d_in, const int* in_sizes, int n_in,
                              void* d_out, int out_size)
{
    const float* q        = (const float*)d_in[0];
    const float* reward   = (const float*)d_in[1];
    const float* discount = (const float*)d_in[2];
    const float* act      = (const float*)d_in[3];
    const float* support  = (const float*)d_in[4];
    const float* low0     = (const float*)d_in[5];
    const float* high0    = (const float*)d_in[6];
    float* out = (float*)d_out;

    cudaFuncSetAttribute(c2f_kernel, cudaFuncAttributeMaxDynamicSharedMemorySize,
                         DYN_BYTES);
    c2f_kernel<<<GRID, THREADS, DYN_BYTES>>>(q, reward, discount, act, support,
                                             low0, high0, out);
}

// round 7
// speedup vs baseline: 2.1503x; 2.1503x over previous
#include <cuda_runtime.h>
#include <cstdint>
#include <math.h>

#define LEVELS 3
#define BINS 9
#define NATOMS 51
#define ADIM 6
#define NB 4096
#define SLAB 8262                 // full per-batch floats (162*51)
#define NTHIRDS 3
#define TROWS 54                  // rows per third
#define TSLAB 2754                // floats per third (54*51)
#define TSLAB_BYTES 11016         // == 8 mod 16
#define LOAD_BYTES 11024          // fixed 16B-multiple bulk-load size
#define INTERIOR_BYTES 11008      // fixed aligned store interior
#define V_MIN_C (-10.0f)
#define V_MAX_C (10.0f)
#define DZ_C (0.4f)

#define THREADS 128
#define GRID (NB * NTHIRDS)       // 12288

// dyn smem (16B-aligned base):
//   [0,16)             mbarrier
//   [16, 16+11024)     input slot  (data at +m)
//   [11040, +11024)    output slot (data at +m)
#define OFF_MBAR 0
#define OFF_IN   16
#define OFF_OUT  (16 + LOAD_BYTES)         // 11040
#define DYN_BYTES (OFF_OUT + LOAD_BYTES)   // 22064

__global__ __launch_bounds__(THREADS)
void c2f_kernel(const float* __restrict__ q,
                const float* __restrict__ reward,
                const float* __restrict__ discount,
                const float* __restrict__ act,
                const float* __restrict__ support,
                const float* __restrict__ low0,
                const float* __restrict__ high0,
                float* __restrict__ out)
{
    const int T = blockIdx.x;             // third index
    const int t = threadIdx.x;
    const int b = T / NTHIRDS;            // batch element
    const int third = T - b * NTHIRDS;
    const int m = (T & 1) ? 8 : 0;        // byte misalignment of T*11016 mod 16

    extern __shared__ __align__(16) char dyn[];
    const uint32_t smem_base = (uint32_t)__cvta_generic_to_shared(dyn);
    const uint32_t mbar = smem_base + OFF_MBAR;

    float* sp = reinterpret_cast<float*>(dyn + OFF_IN  + m);
    float* so = reinterpret_cast<float*>(dyn + OFF_OUT + m);

    __shared__ float swl[NATOMS];
    __shared__ float swu[NATOMS];
    __shared__ int   slower[NATOMS];

    if (t == 0) {
        asm volatile("mbarrier.init.shared.b64 [%0], 1;" :: "r"(mbar) : "memory");
    }

    // ---- projection tables (block-uniform; depend only on b) ----
    if (t < NATOMS) {
        const float r = reward[b];
        const float d = discount[b];
        const float z = support[t];
        float Tz = fminf(fmaxf(r + d * z, V_MIN_C), V_MAX_C);
        float bc = (Tz - V_MIN_C) / DZ_C;
        int lo = (int)floorf(bc);
        int up = (int)ceilf(bc);
        if (up > 0 && lo == up) lo -= 1;              // reference fixup 1
        if (lo < NATOMS - 1 && lo == up) up += 1;     // reference fixup 2 => up==lo+1
        slower[t] = lo;                               // in [0,49]
        swl[t] = (float)up - bc;
        swu[t] = bc - (float)lo;
    }

    // ---- encode + decode: only in the third==0 CTA of each batch element ----
    if (third == 0 && t >= 64 && t < 64 + ADIM) {
        const int dim = t - 64;
        const float a = act[b * ADIM + dim];
        float low = low0[dim], high = high0[dim];
        float idx[LEVELS];
        #pragma unroll
        for (int lvl = 0; lvl < LEVELS; lvl++) {
            float sr = (high - low) / (float)BINS;
            float id = floorf((a - low) / sr);
            id = fminf(fmaxf(id, 0.0f), (float)(BINS - 1));
            float na = fminf(fmaxf(low + sr * id, -1.0f), 1.0f);
            low  = fmaxf(-1.0f, na);
            high = fminf(1.0f, na + sr);
            idx[lvl] = id;
        }
        low = low0[dim]; high = high0[dim];
        #pragma unroll
        for (int lvl = 0; lvl < LEVELS; lvl++) {
            float sr = (high - low) / (float)BINS;
            float cont = low + sr * idx[lvl];
            low  = fmaxf(-1.0f, cont);
            high = fminf(1.0f, cont + sr);
        }
        out[(size_t)NB * SLAB + (size_t)b * ADIM + dim] = 0.5f * (high + low);
    }

    __syncthreads();   // mbar init visible

    // ---- TMA bulk load: aligned-down source, fixed 11024 B ----
    if (t == 0) {
        const char* src = reinterpret_cast<const char*>(q) + (size_t)T * TSLAB_BYTES - m;
        asm volatile("mbarrier.arrive.expect_tx.shared.b64 _, [%0], %1;"
                     :: "r"(mbar), "r"((uint32_t)LOAD_BYTES) : "memory");
        asm volatile("cp.async.bulk.shared::cta.global.mbarrier::complete_tx::bytes "
                     "[%0], [%1], %2, [%3];"
                     :: "r"(smem_base + OFF_IN), "l"(src),
                        "r"((uint32_t)LOAD_BYTES), "r"(mbar) : "memory");
    }

    // ---- wait for the third-slab ----
    asm volatile(
        "{\n\t"
        ".reg .pred P;\n\t"
        "WAIT_%=:\n\t"
        "mbarrier.try_wait.parity.acquire.cta.shared::cta.b64 P, [%0], 0, 0x989680;\n\t"
        "@!P bra WAIT_%=;\n\t"
        "}"
        :: "r"(mbar) : "memory");

    // ---- walk: one thread per row, single pass j=0..50, gap zero-fill ----
    if (t < TROWS) {
        const float* pr = sp + t * NATOMS;   // stride 51 (odd) -> conflict-free
        float* po = so + t * NATOMS;
        int kcur = slower[0];
        for (int k = 0; k < kcur; k++) po[k] = 0.0f;
        float accA = 0.0f, accB = 0.0f, carryB = 0.0f;
        #pragma unroll 1
        for (int j = 0; j < NATOMS; j++) {
            const int kj = slower[j];        // uniform broadcast
            if (kj != kcur) {                // uniform branch
                po[kcur] = accA + carryB;
                if (kj == kcur + 1) {
                    carryB = accB;
                } else {
                    po[kcur + 1] = accB;
                    for (int k = kcur + 2; k < kj; k++) po[k] = 0.0f;
                    carryB = 0.0f;
                }
                accA = 0.0f; accB = 0.0f; kcur = kj;
            }
            const float p = pr[j];
            accA = fmaf(p, swl[j], accA);
            accB = fmaf(p, swu[j], accB);
        }
        po[kcur] = accA + carryB;
        po[kcur + 1] = accB;                 // kcur <= 49 -> safe
        for (int k = kcur + 2; k < NATOMS; k++) po[k] = 0.0f;
    }
    __syncthreads();

    // ---- store: 2 scalar floats (head or tail) + 11008 B aligned bulk ----
    if (t == 0) {
        float* dst = out + (size_t)T * TSLAB;
        if (m == 8) {                        // head 2 floats reach alignment
            dst[0] = so[0];
            dst[1] = so[1];
        } else {                             // tail 2 floats
            dst[TSLAB - 2] = so[TSLAB - 2];
            dst[TSLAB - 1] = so[TSLAB - 1];
        }
        asm volatile("fence.proxy.async.shared::cta;" ::: "memory");
        const int hb = (m == 8) ? 8 : 0;     // head bytes skipped
        const uint32_t src_s = smem_base + OFF_OUT + (uint32_t)(m + hb);  // 0 or 16
        char* dst_al = reinterpret_cast<char*>(out) + (size_t)T * TSLAB_BYTES + hb;
        asm volatile("cp.async.bulk.global.shared::cta.bulk_group [%0], [%1], %2;"
                     :: "l"(dst_al), "r"(src_s), "r"((uint32_t)INTERIOR_BYTES) : "memory");
        asm volatile("cp.async.bulk.commit_group;" ::: "memory");
        asm volatile("cp.async.bulk.wait_group 0;" ::: "memory");
    }
}

extern "C" void kernel_launch(void* const* d_in, const int* in_sizes, int n_in,
                              void* d_out, int out_size)
{
    const float* q        = (const float*)d_in[0];
    const float* reward   = (const float*)d_in[1];
    const float* discount = (const float*)d_in[2];
    const float* act      = (const float*)d_in[3];
    const float* support  = (const float*)d_in[4];
    const float* low0     = (const float*)d_in[5];
    const float* high0    = (const float*)d_in[6];
    float* out = (float*)d_out;

    cudaFuncSetAttribute(c2f_kernel, cudaFuncAttributeMaxDynamicSharedMemorySize,
                         DYN_BYTES);
    c2f_kernel<<<GRID, THREADS, DYN_BYTES>>>(q, reward, discount, act, support,
                                             low0, high0, out);
}

// round 8
// speedup vs baseline: 2.2720x; 1.0566x over previous
#include <cuda_runtime.h>
#include <cstdint>
#include <math.h>

#define LEVELS 3
#define BINS 9
#define NATOMS 51
#define ADIM 6
#define NB 4096
#define SLAB 8262                 // full per-batch floats (162*51)
#define NSIX 6
#define TROWS 27                  // rows per sixth
#define TSLAB 1377                // floats per sixth (27*51)
#define TSLAB_BYTES 5508          // == 4 mod 16
#define LOAD_BYTES 5520           // fixed 16B-multiple bulk-load size
#define V_MIN_C (-10.0f)
#define V_MAX_C (10.0f)
#define DZ_C (0.4f)

#define THREADS 64
#define GRID (NB * NSIX)          // 24576

// dyn smem (16B-aligned base):
//   [0,16)            mbarrier
//   [16, 16+5520)     input slot  (data at +m)
//   [5536, +5520)     output slot (data at +m)
#define OFF_MBAR 0
#define OFF_IN   16
#define OFF_OUT  (16 + LOAD_BYTES)         // 5536
#define DYN_BYTES (OFF_OUT + LOAD_BYTES)   // 11056

__global__ __launch_bounds__(THREADS)
void c2f_kernel(const float* __restrict__ q,
                const float* __restrict__ reward,
                const float* __restrict__ discount,
                const float* __restrict__ act,
                const float* __restrict__ support,
                const float* __restrict__ low0,
                const float* __restrict__ high0,
                float* __restrict__ out)
{
    const int T = blockIdx.x;             // sixth index
    const int t = threadIdx.x;
    const int b = T / NSIX;               // batch element
    const int sixth = T - b * NSIX;
    const int m = (T & 3) * 4;            // byte misalignment of T*5508 mod 16

    extern __shared__ __align__(16) char dyn[];
    const uint32_t smem_base = (uint32_t)__cvta_generic_to_shared(dyn);
    const uint32_t mbar = smem_base + OFF_MBAR;

    float* sp = reinterpret_cast<float*>(dyn + OFF_IN  + m);
    float* so = reinterpret_cast<float*>(dyn + OFF_OUT + m);

    __shared__ __align__(16) float4 stbl[NATOMS];   // (wl, wu, lower_bits, 0)

    // ---- t0: init mbar, fire TMA immediately (tables overlap the flight) ----
    if (t == 0) {
        asm volatile("mbarrier.init.shared.b64 [%0], 1;" :: "r"(mbar) : "memory");
        const char* src = reinterpret_cast<const char*>(q) + (size_t)T * TSLAB_BYTES - m;
        asm volatile("mbarrier.arrive.expect_tx.shared.b64 _, [%0], %1;"
                     :: "r"(mbar), "r"((uint32_t)LOAD_BYTES) : "memory");
        asm volatile("cp.async.bulk.shared::cta.global.mbarrier::complete_tx::bytes "
                     "[%0], [%1], %2, [%3];"
                     :: "r"(smem_base + OFF_IN), "l"(src),
                        "r"((uint32_t)LOAD_BYTES), "r"(mbar) : "memory");
    }

    // ---- projection table (block-uniform; depends only on b) ----
    if (t < NATOMS) {
        const float r = reward[b];
        const float d = discount[b];
        const float z = support[t];
        float Tz = fminf(fmaxf(r + d * z, V_MIN_C), V_MAX_C);
        float bc = (Tz - V_MIN_C) / DZ_C;
        int lo = (int)floorf(bc);
        int up = (int)ceilf(bc);
        if (up > 0 && lo == up) lo -= 1;              // reference fixup 1
        if (lo < NATOMS - 1 && lo == up) up += 1;     // reference fixup 2 => up==lo+1
        stbl[t] = make_float4((float)up - bc, bc - (float)lo,
                              __int_as_float(lo), 0.0f);
    }

    // ---- encode + decode: only in the sixth==0 CTA of each batch element ----
    if (sixth == 0 && t >= 52 && t < 52 + ADIM) {
        const int dim = t - 52;
        const float a = act[b * ADIM + dim];
        float low = low0[dim], high = high0[dim];
        float idx[LEVELS];
        #pragma unroll
        for (int lvl = 0; lvl < LEVELS; lvl++) {
            float sr = (high - low) / (float)BINS;
            float id = floorf((a - low) / sr);
            id = fminf(fmaxf(id, 0.0f), (float)(BINS - 1));
            float na = fminf(fmaxf(low + sr * id, -1.0f), 1.0f);
            low  = fmaxf(-1.0f, na);
            high = fminf(1.0f, na + sr);
            idx[lvl] = id;
        }
        low = low0[dim]; high = high0[dim];
        #pragma unroll
        for (int lvl = 0; lvl < LEVELS; lvl++) {
            float sr = (high - low) / (float)BINS;
            float cont = low + sr * idx[lvl];
            low  = fmaxf(-1.0f, cont);
            high = fminf(1.0f, cont + sr);
        }
        out[(size_t)NB * SLAB + (size_t)b * ADIM + dim] = 0.5f * (high + low);
    }

    __syncthreads();   // mbar init + table visible to all

    // ---- wait for the slab ----
    asm volatile(
        "{\n\t"
        ".reg .pred P;\n\t"
        "WAIT_%=:\n\t"
        "mbarrier.try_wait.parity.acquire.cta.shared::cta.b64 P, [%0], 0, 0x989680;\n\t"
        "@!P bra WAIT_%=;\n\t"
        "}"
        :: "r"(mbar) : "memory");

    // ---- walk: one thread per row, single pass j=0..50, gap zero-fill ----
    if (t < TROWS) {
        const float* pr = sp + t * NATOMS;   // stride 51 (odd) -> conflict-free
        float* po = so + t * NATOMS;
        int kcur = __float_as_int(stbl[0].z);
        for (int k = 0; k < kcur; k++) po[k] = 0.0f;
        float accA = 0.0f, accB = 0.0f, carryB = 0.0f;
        #pragma unroll 1
        for (int j = 0; j < NATOMS; j++) {
            const float4 tb = stbl[j];       // LDS.128 broadcast
            const int kj = __float_as_int(tb.z);
            if (kj != kcur) {                // uniform branch
                po[kcur] = accA + carryB;
                if (kj == kcur + 1) {
                    carryB = accB;
                } else {
                    po[kcur + 1] = accB;
                    for (int k = kcur + 2; k < kj; k++) po[k] = 0.0f;
                    carryB = 0.0f;
                }
                accA = 0.0f; accB = 0.0f; kcur = kj;
            }
            const float p = pr[j];
            accA = fmaf(p, tb.x, accA);
            accB = fmaf(p, tb.y, accB);
        }
        po[kcur] = accA + carryB;
        po[kcur + 1] = accB;                 // kcur <= 49 -> safe
        for (int k = kcur + 2; k < NATOMS; k++) po[k] = 0.0f;
    }
    __syncthreads();

    // ---- store: h head + tail scalar floats, aligned interior via bulk ----
    const int h = ((16 - m) & 15) >> 2;               // head floats (0..3)
    const int rem = TSLAB_BYTES - h * 4;
    const int interior = rem & ~15;
    const int tailf = (rem & 15) >> 2;                // tail floats (0..3)
    if (t < 4) {
        float* dst = out + (size_t)T * TSLAB;
        if (t < h)     dst[t] = so[t];
        if (t < tailf) dst[TSLAB - 1 - t] = so[TSLAB - 1 - t];
    }
    if (t == 0) {
        asm volatile("fence.proxy.async.shared::cta;" ::: "memory");
        const uint32_t src_s = smem_base + OFF_OUT + (uint32_t)(m + h * 4); // 16B aligned
        char* dst_al = reinterpret_cast<char*>(out) + (size_t)T * TSLAB_BYTES + h * 4;
        asm volatile("cp.async.bulk.global.shared::cta.bulk_group [%0], [%1], %2;"
                     :: "l"(dst_al), "r"(src_s), "r"((uint32_t)interior) : "memory");
        asm volatile("cp.async.bulk.commit_group;" ::: "memory");
        asm volatile("cp.async.bulk.wait_group 0;" ::: "memory");
    }
}

extern "C" void kernel_launch(void* const* d_in, const int* in_sizes, int n_in,
                              void* d_out, int out_size)
{
    const float* q        = (const float*)d_in[0];
    const float* reward   = (const float*)d_in[1];
    const float* discount = (const float*)d_in[2];
    const float* act      = (const float*)d_in[3];
    const float* support  = (const float*)d_in[4];
    const float* low0     = (const float*)d_in[5];
    const float* high0    = (const float*)d_in[6];
    float* out = (float*)d_out;

    cudaFuncSetAttribute(c2f_kernel, cudaFuncAttributeMaxDynamicSharedMemorySize,
                         DYN_BYTES);
    c2f_kernel<<<GRID, THREADS, DYN_BYTES>>>(q, reward, discount, act, support,
                                             low0, high0, out);
}